// round 15
// baseline (speedup 1.0000x reference)
#include <cuda_runtime.h>
#include <cstdint>

// Problem sizes
#define S    4096
#define II   64
#define H    1024
#define NCTA 128
#define UPC  8        // hidden units per CTA (1 per warp, 8 warps)

// ---------------------------------------------------------------------------
// Device-global scratch (allocation-free rule: __device__ arrays only)
//
// CHAMPION R8 GLOBAL PROTOCOL — DO NOT TOUCH (6 structural variants lost):
//   g_hq: double-buffered tagged atoms {h:f32 | tag:u32}; h_t in slot t&1,
//         tag==t. st/ld.relaxed.gpu.b64 only (single-copy atomic).
//   g_cnt: ADVISORY counter; 1 polling warp per CTA on ONE line, 128
//         relaxed REDs per step. Tags carry ALL correctness; counter only
//         prevents sweep flood. Zero acquire/release anywhere = zero
//         ordering-drain stalls (this is why R8 beats every strong variant).
// ---------------------------------------------------------------------------
__device__ unsigned long long g_hq[2][H];
__device__ unsigned g_cnt;

// ---------------------------------------------------------------------------
// Helpers
// ---------------------------------------------------------------------------
__device__ __forceinline__ unsigned long long pk2(float x, float y) {
    unsigned long long r;
    asm("mov.b64 %0, {%1,%2};" : "=l"(r) : "f"(x), "f"(y));
    return r;
}
__device__ __forceinline__ void upk2(unsigned long long a, float& x, float& y) {
    asm("mov.b64 {%0,%1}, %2;" : "=f"(x), "=f"(y) : "l"(a));
}
__device__ __forceinline__ unsigned long long pk_fu(float x, unsigned t) {
    unsigned long long r;
    asm("mov.b64 %0, {%1,%2};" : "=l"(r) : "f"(x), "r"(t));
    return r;
}
#define FMA2(acc, a, b) \
    asm("fma.rn.f32x2 %0, %1, %2, %0;" : "+l"(acc) : "l"(a), "l"(b))

__device__ __forceinline__ float sigf(float x) {
    return 1.0f / (1.0f + __expf(-x));
}
__device__ __forceinline__ float tanhfast(float x) {
    float ax = fabsf(x);
    float e  = __expf(-2.0f * ax);          // in (0,1], overflow-free
    float t  = __fdividef(1.0f - e, 1.0f + e);
    return copysignf(t, x);
}

// ---------------------------------------------------------------------------
// Kernel 0: reset state between graph replays (determinism requirement)
// slot 0: tag 0 / h = 0  ->  step-0 sweep passes immediately with h_0 = 0.
// ---------------------------------------------------------------------------
__global__ void reset_kernel() {
    int i = threadIdx.x;
    if (i < H) { g_hq[0][i] = 0ull; g_hq[1][i] = 0ull; }
    if (i == 0) g_cnt = 0u;
}

// ---------------------------------------------------------------------------
// Kernel 1: persistent fused LSTM recurrence (input GEMM folded in).
// 128 CTAs x 256 threads, 1 CTA/SM. Warp w of CTA b owns hidden unit
// u = b*8 + w (gate rows u, H+u, 2H+u, 3H+u). Lane l holds W_hh column
// pairs (2l+64k) k=0..15 (64 packed f32x2) + W_ih column pair 2l in regs.
//
// Per-step protocol (TWO __syncthreads; R8 had three):
//   1. prefetch x_{t+1} (tid<16, 256 B, triple-buffered SMEM)
//   2. GATE: warp 0 (all lanes, ONE coalesced broadcast req/iter) polls
//      relaxed g_cnt >= 128*t; lane 0 writes volatile SMEM flag = t.
//      Warps 1-7 spin on the flag (~30cy LDS) — replaces bar A's ~100cy+
//      wakeup. Flag needs no ordering: the tagged sweep self-validates.
//   3. SWEEP: 4 scalar ld.relaxed.b64 tagged atoms per thread, retry if
//      stale (rare; gate is exact) -> tag+data in one L2 round trip
//   4. stage h -> hs[t&1] (STS.128); __syncthreads (bar B)
//   5. matvec (LDS.64 + FMA2, W_hh + W_ih) -> butterfly shfl reduce
//   6. ACTIVATIONS IN PARALLEL: lanes 0-3 each compute one gate act
//      (~55cy concurrent vs ~220cy serial); lane 0 gathers via 4 shfls,
//      updates c, computes h = o*tanh(c), publishes {h, t+1} via
//      st.relaxed.gpu.b64 into slot (t+1)&1
//   7. trailing __syncthreads; tid 0: red.relaxed.gpu.add(g_cnt, 1)
//
// Gate exactness: cnt >= 128t iff every CTA finished step t-1 (trailing
// bar orders each CTA's red after all 8 publishes). Phase-mixing: bar B +
// trailing bar = 2 rendezvous/step, warp skew < 1 step; hs double-buffer
// and xs triple-buffer cover it. WAR on g_hq slots: R7/R8 argument
// (a slot is rewritten only after every reader's step, gated by the exact
// counter, completed). Correctness backstop everywhere: tags.
// ---------------------------------------------------------------------------
__global__ void __launch_bounds__(256, 1) rec_kernel(
    const float* __restrict__ x,
    const float* __restrict__ Wih,
    const float* __restrict__ Whh,
    const float* __restrict__ bih,
    const float* __restrict__ bhh)
{
    __shared__ __align__(16) float hs[2][H];     // staged h_t
    __shared__ __align__(16) float xs[3][II];    // staged x_t (triple buffer)
    __shared__ unsigned gflag;                   // monotonic step flag (fanout)

    const int tid  = threadIdx.x;
    const int lane = tid & 31;
    const int wrp  = tid >> 5;               // 0..7
    const int u    = blockIdx.x * UPC + wrp; // hidden unit 0..1023

    const unsigned fa = (unsigned)__cvta_generic_to_shared(&gflag);

    // ---- W_hh slice into registers (coalesced float2 loads) ----
    unsigned long long wq[4][16];
    #pragma unroll
    for (int g = 0; g < 4; g++) {
        const float2* base = (const float2*)(Whh + (size_t)(g * H + u) * H) + lane;
        #pragma unroll
        for (int k = 0; k < 16; k++) {
            float2 v = base[k * 32];
            wq[g][k] = pk2(v.x, v.y);
        }
    }
    // ---- W_ih slice (cols 2l, 2l+1 of rows u, H+u, 2H+u, 3H+u) ----
    unsigned long long wx[4];
    #pragma unroll
    for (int g = 0; g < 4; g++) {
        float2 v = ((const float2*)(Wih + (size_t)(g * H + u) * II))[lane];
        wx[g] = pk2(v.x, v.y);
    }
    // ---- biases (all lanes hold all four; needed for parallel acts) ----
    float bs0 = bih[u]         + bhh[u];
    float bs1 = bih[H + u]     + bhh[H + u];
    float bs2 = bih[2 * H + u] + bhh[2 * H + u];
    float bs3 = bih[3 * H + u] + bhh[3 * H + u];

    // ---- preload x_0, init flag ----
    if (tid < 16) ((float4*)xs[0])[tid] = ((const float4*)x)[tid];
    if (tid == 0) gflag = 0u;
    __syncthreads();

    float c = 0.0f;                          // cell state (lane 0 only)
    const unsigned full = 0xffffffffu;

    const unsigned long long* mypoll = &g_hq[0][0] + 4 * tid;  // + slot*H per step

    #pragma unroll 1
    for (int t = 0; t < S; t++) {
        const int cur = t & 1;

        // 1. prefetch next step's input row (DRAM, hidden behind this step)
        if (t + 1 < S && tid < 16)
            ((float4*)xs[(t + 1) % 3])[tid] =
                __ldcg((const float4*)(x + (size_t)(t + 1) * II) + tid);

        // 2. GATE with SMEM flag fanout (advisory; tags backstop correctness)
        if (t > 0) {
            if (wrp == 0) {
                // whole warp polls one address: 1 broadcast request per iter
                const unsigned need = (unsigned)t * NCTA;
                unsigned v;
                do {
                    asm volatile("ld.relaxed.gpu.global.u32 %0, [%1];"
                                 : "=r"(v) : "l"(&g_cnt));
                } while (v < need);
                if (lane == 0)
                    asm volatile("st.volatile.shared.u32 [%0], %1;"
                                 :: "r"(fa), "r"((unsigned)t));
            } else {
                unsigned f;
                do {
                    asm volatile("ld.volatile.shared.u32 %0, [%1];"
                                 : "=r"(f) : "r"(fa));
                } while (f < (unsigned)t);
            }
        }

        // 3. SWEEP: 4 tagged atoms per thread (relaxed, MLP'd); rare retry
        const unsigned long long* p = mypoll + (size_t)cur * H;
        unsigned long long q0, q1, q2, q3;
        do {
            asm volatile("ld.relaxed.gpu.global.b64 %0, [%1];" : "=l"(q0) : "l"(p));
            asm volatile("ld.relaxed.gpu.global.b64 %0, [%1];" : "=l"(q1) : "l"(p + 1));
            asm volatile("ld.relaxed.gpu.global.b64 %0, [%1];" : "=l"(q2) : "l"(p + 2));
            asm volatile("ld.relaxed.gpu.global.b64 %0, [%1];" : "=l"(q3) : "l"(p + 3));
        } while ((unsigned)(q0 >> 32) != (unsigned)t ||
                 (unsigned)(q1 >> 32) != (unsigned)t ||
                 (unsigned)(q2 >> 32) != (unsigned)t ||
                 (unsigned)(q3 >> 32) != (unsigned)t);

        // 4. stage into SMEM
        float4 hv4;
        hv4.x = __uint_as_float((unsigned)q0);
        hv4.y = __uint_as_float((unsigned)q1);
        hv4.z = __uint_as_float((unsigned)q2);
        hv4.w = __uint_as_float((unsigned)q3);
        ((float4*)hs[cur])[tid] = hv4;
        __syncthreads();                     // bar B

        // 5. mat-vec: W_hh * h_t  +  W_ih * x_t  (all packed f32x2)
        unsigned long long a0 = 0ull, a1 = 0ull, a2 = 0ull, a3 = 0ull;
        const unsigned long long* h2p = (const unsigned long long*)hs[cur] + lane;
        #pragma unroll
        for (int k = 0; k < 16; k++) {
            unsigned long long hv = h2p[k * 32];
            FMA2(a0, wq[0][k], hv);
            FMA2(a1, wq[1][k], hv);
            FMA2(a2, wq[2][k], hv);
            FMA2(a3, wq[3][k], hv);
        }
        {
            unsigned long long xv = ((const unsigned long long*)xs[t % 3])[lane];
            FMA2(a0, wx[0], xv);
            FMA2(a1, wx[1], xv);
            FMA2(a2, wx[2], xv);
            FMA2(a3, wx[3], xv);
        }
        float s0, s1, s2, s3, xl, xh;
        upk2(a0, xl, xh); s0 = xl + xh;
        upk2(a1, xl, xh); s1 = xl + xh;
        upk2(a2, xl, xh); s2 = xl + xh;
        upk2(a3, xl, xh); s3 = xl + xh;

        #pragma unroll
        for (int off = 16; off > 0; off >>= 1) {
            s0 += __shfl_xor_sync(full, s0, off);
            s1 += __shfl_xor_sync(full, s1, off);
            s2 += __shfl_xor_sync(full, s2, off);
            s3 += __shfl_xor_sync(full, s3, off);
        }
        // post-butterfly: every lane holds the full s0..s3

        // 6. parallel activations (lanes 0-3), gather, c-update, publish
        {
            const int r = lane & 3;
            float pre = (r == 0) ? s0 + bs0 :
                        (r == 1) ? s1 + bs1 :
                        (r == 2) ? s2 + bs2 : s3 + bs3;
            float act = (r == 2) ? tanhfast(pre) : sigf(pre);
            const float i_ = __shfl_sync(full, act, 0);
            const float f_ = __shfl_sync(full, act, 1);
            const float g_ = __shfl_sync(full, act, 2);
            const float o_ = __shfl_sync(full, act, 3);
            if (lane == 0) {
                c = fmaf(f_, c, i_ * g_);
                const float hnew = o_ * tanhfast(c);
                unsigned long long pub = pk_fu(hnew, (unsigned)(t + 1));
                asm volatile("st.relaxed.gpu.global.b64 [%0], %1;"
                             :: "l"(&g_hq[(t + 1) & 1][u]), "l"(pub));
            }
        }

        // 7. trailing bar + single advisory counter bump
        __syncthreads();
        if (tid == 0)
            asm volatile("red.relaxed.gpu.global.add.u32 [%0], %1;"
                         :: "l"(&g_cnt), "r"(1u));
    }
}

// ---------------------------------------------------------------------------
// Kernel 2: out = h_S @ W_lin^T + b_lin   (O = 1)
// h_S lives in g_hq[S & 1] = g_hq[0] (tag field ignored)
// ---------------------------------------------------------------------------
__global__ void __launch_bounds__(1024) out_kernel(
    const float* __restrict__ Wlin,
    const float* __restrict__ blin,
    float* __restrict__ out)
{
    __shared__ float red[32];
    const int tid = threadIdx.x;
    float h = __uint_as_float((unsigned)(g_hq[0][tid] & 0xffffffffull));
    float v = h * Wlin[tid];
    #pragma unroll
    for (int off = 16; off > 0; off >>= 1)
        v += __shfl_xor_sync(0xffffffffu, v, off);
    if ((tid & 31) == 0) red[tid >> 5] = v;
    __syncthreads();
    if (tid < 32) {
        float xv = red[tid];
        #pragma unroll
        for (int off = 16; off > 0; off >>= 1)
            xv += __shfl_xor_sync(0xffffffffu, xv, off);
        if (tid == 0) out[0] = xv + blin[0];
    }
}

// ---------------------------------------------------------------------------
// kernel_launch (graph-capturable: plain launches only)
// Input order: input_seq, W_ih, W_hh, b_ih, b_hh, W_lin, b_lin (all fp32)
// ---------------------------------------------------------------------------
extern "C" void kernel_launch(void* const* d_in, const int* in_sizes, int n_in,
                              void* d_out, int out_size)
{
    const float* x    = (const float*)d_in[0];
    const float* Wih  = (const float*)d_in[1];
    const float* Whh  = (const float*)d_in[2];
    const float* bih  = (const float*)d_in[3];
    const float* bhh  = (const float*)d_in[4];
    const float* Wlin = (const float*)d_in[5];
    const float* blin = (const float*)d_in[6];
    float* out = (float*)d_out;

    reset_kernel<<<1, 1024>>>();
    rec_kernel<<<NCTA, 256>>>(x, Wih, Whh, bih, bhh);
    out_kernel<<<1, 1024>>>(Wlin, blin, out);
}

// round 16
// speedup vs baseline: 1.0147x; 1.0147x over previous
#include <cuda_runtime.h>
#include <cstdint>

// Problem sizes
#define S    4096
#define II   64
#define H    1024
#define NCTA 128
#define UPC  8        // hidden units per CTA (1 per warp, 8 warps)

// ---------------------------------------------------------------------------
// Device-global scratch (allocation-free rule: __device__ arrays only)
//
// CHAMPION R8 GLOBAL PROTOCOL — UNCHANGED (7 structural variants all lost):
//   g_hq: double-buffered tagged atoms {h:f32 | tag:u32}; h_t in slot t&1,
//         tag==t. st/ld.relaxed.gpu.b64 only (morally strong <=64b =>
//         single-copy atomic). Tags carry ALL correctness.
//   g_cnt: ADVISORY counter; exactly ONE polling LANE per CTA (128 chip-
//         wide) + 128 relaxed REDs per step on ONE line. Discovery law
//         (R3/R7/R9/R11/R12/R13/R15): any more strong pollers regresses.
//
// R16 delta vs R8 (on-SM only, zero global-traffic change): bar A replaced
// by a volatile SMEM flag written by the sole poller; other threads spin on
// a ~30cy broadcast LDS loop instead of paying the full-barrier wakeup.
// ---------------------------------------------------------------------------
__device__ unsigned long long g_hq[2][H];
__device__ unsigned g_cnt;

// ---------------------------------------------------------------------------
// Helpers
// ---------------------------------------------------------------------------
__device__ __forceinline__ unsigned long long pk2(float x, float y) {
    unsigned long long r;
    asm("mov.b64 %0, {%1,%2};" : "=l"(r) : "f"(x), "f"(y));
    return r;
}
__device__ __forceinline__ void upk2(unsigned long long a, float& x, float& y) {
    asm("mov.b64 {%0,%1}, %2;" : "=f"(x), "=f"(y) : "l"(a));
}
__device__ __forceinline__ unsigned long long pk_fu(float x, unsigned t) {
    unsigned long long r;
    asm("mov.b64 %0, {%1,%2};" : "=l"(r) : "f"(x), "r"(t));
    return r;
}
#define FMA2(acc, a, b) \
    asm("fma.rn.f32x2 %0, %1, %2, %0;" : "+l"(acc) : "l"(a), "l"(b))

__device__ __forceinline__ float sigf(float x) {
    return 1.0f / (1.0f + __expf(-x));
}
__device__ __forceinline__ float tanhfast(float x) {
    float ax = fabsf(x);
    float e  = __expf(-2.0f * ax);          // in (0,1], overflow-free
    float t  = __fdividef(1.0f - e, 1.0f + e);
    return copysignf(t, x);
}

// ---------------------------------------------------------------------------
// Kernel 0: reset state between graph replays (determinism requirement)
// slot 0: tag 0 / h = 0  ->  step-0 sweep passes immediately with h_0 = 0.
// ---------------------------------------------------------------------------
__global__ void reset_kernel() {
    int i = threadIdx.x;
    if (i < H) { g_hq[0][i] = 0ull; g_hq[1][i] = 0ull; }
    if (i == 0) g_cnt = 0u;
}

// ---------------------------------------------------------------------------
// Kernel 1: persistent fused LSTM recurrence (input GEMM folded in).
// 128 CTAs x 256 threads, 1 CTA/SM. Warp w of CTA b owns hidden unit
// u = b*8 + w (gate rows u, H+u, 2H+u, 3H+u). Lane l holds W_hh column
// pairs (2l+64k) k=0..15 (64 packed f32x2) + W_ih column pair 2l in regs.
//
// Per-step protocol (TWO __syncthreads; R8 had three):
//   1. prefetch x_{t+1} (tid<16, 256 B, triple-buffered SMEM)
//   2. GATE: tid 0 — the ONLY global poller — spins relaxed on g_cnt until
//      >= 128*t, then writes volatile SMEM flag = t. ALL other threads
//      (incl. warp 0 lanes 1-31) spin on the broadcast LDS flag (~30cy).
//      Flag and counter are both advisory: the tagged sweep self-validates.
//   3. SWEEP: 4 scalar ld.relaxed.b64 tagged atoms per thread, retry if a
//      tag is stale (rare post-gate) -> tag+data in one L2 round trip
//   4. stage h -> hs[t&1] (STS.128); __syncthreads (bar B)
//   5. matvec (LDS.64 + FMA2, W_hh + W_ih) -> butterfly shfl reduce
//   6. lane 0: activations, c-update, publish {h_new, t+1} via
//      st.relaxed.gpu.b64 into slot (t+1)&1
//   7. trailing __syncthreads (bar C); tid 0: red.relaxed.gpu.add(g_cnt,1)
//
// Gate exactness: cnt >= 128t iff every CTA finished step t-1 (bar C
// orders each CTA's red after all 8 publishes). Phase alignment without
// bar A: bars B and C bound warp skew to < 1 step, and tid 0 writes
// flag = t only in its own step-t gate phase, so no warp can see a flag
// for a step it hasn't reached. hs WAR: hs[t&1] was last read in step t-2,
// separated by bar C(t-2) + bar B(t-1) + bar C(t-1) from the step-t STS.
// g_hq slot WAR: R7/R8 argument — a slot is rewritten only after every
// reader of its previous occupancy completed (counter-gated), and any
// residual race is caught by the tag retry. Correctness backstop: tags.
// ---------------------------------------------------------------------------
__global__ void __launch_bounds__(256, 1) rec_kernel(
    const float* __restrict__ x,
    const float* __restrict__ Wih,
    const float* __restrict__ Whh,
    const float* __restrict__ bih,
    const float* __restrict__ bhh)
{
    __shared__ __align__(16) float hs[2][H];     // staged h_t
    __shared__ __align__(16) float xs[3][II];    // staged x_t (triple buffer)
    __shared__ unsigned gflag;                   // monotonic step flag (fanout)

    const int tid  = threadIdx.x;
    const int lane = tid & 31;
    const int wrp  = tid >> 5;               // 0..7
    const int u    = blockIdx.x * UPC + wrp; // hidden unit 0..1023

    const unsigned fa = (unsigned)__cvta_generic_to_shared(&gflag);

    // ---- W_hh slice into registers (coalesced float2 loads) ----
    unsigned long long wq[4][16];
    #pragma unroll
    for (int g = 0; g < 4; g++) {
        const float2* base = (const float2*)(Whh + (size_t)(g * H + u) * H) + lane;
        #pragma unroll
        for (int k = 0; k < 16; k++) {
            float2 v = base[k * 32];
            wq[g][k] = pk2(v.x, v.y);
        }
    }
    // ---- W_ih slice (cols 2l, 2l+1 of rows u, H+u, 2H+u, 3H+u) ----
    unsigned long long wx[4];
    #pragma unroll
    for (int g = 0; g < 4; g++) {
        float2 v = ((const float2*)(Wih + (size_t)(g * H + u) * II))[lane];
        wx[g] = pk2(v.x, v.y);
    }
    // ---- biases (only lane 0 consumes them) ----
    float bs0 = bih[u]         + bhh[u];
    float bs1 = bih[H + u]     + bhh[H + u];
    float bs2 = bih[2 * H + u] + bhh[2 * H + u];
    float bs3 = bih[3 * H + u] + bhh[3 * H + u];

    // ---- preload x_0, init flag ----
    if (tid < 16) ((float4*)xs[0])[tid] = ((const float4*)x)[tid];
    if (tid == 0) gflag = 0u;
    __syncthreads();

    float c = 0.0f;                          // cell state (lane 0 only)
    const unsigned full = 0xffffffffu;

    const unsigned long long* mypoll = &g_hq[0][0] + 4 * tid;  // + slot*H per step

    #pragma unroll 1
    for (int t = 0; t < S; t++) {
        const int cur = t & 1;

        // 1. prefetch next step's input row (DRAM, hidden behind this step)
        if (t + 1 < S && tid < 16)
            ((float4*)xs[(t + 1) % 3])[tid] =
                __ldcg((const float4*)(x + (size_t)(t + 1) * II) + tid);

        // 2. GATE: sole poller tid 0 -> volatile SMEM flag fanout
        if (t > 0) {
            if (tid == 0) {
                const unsigned need = (unsigned)t * NCTA;
                unsigned v;
                do {
                    asm volatile("ld.relaxed.gpu.global.u32 %0, [%1];"
                                 : "=r"(v) : "l"(&g_cnt));
                } while (v < need);
                asm volatile("st.volatile.shared.u32 [%0], %1;"
                             :: "r"(fa), "r"((unsigned)t));
            } else {
                unsigned f;
                do {
                    asm volatile("ld.volatile.shared.u32 %0, [%1];"
                                 : "=r"(f) : "r"(fa));
                } while (f < (unsigned)t);
            }
        }

        // 3. SWEEP: 4 tagged atoms per thread (relaxed, MLP'd); rare retry
        const unsigned long long* p = mypoll + (size_t)cur * H;
        unsigned long long q0, q1, q2, q3;
        do {
            asm volatile("ld.relaxed.gpu.global.b64 %0, [%1];" : "=l"(q0) : "l"(p));
            asm volatile("ld.relaxed.gpu.global.b64 %0, [%1];" : "=l"(q1) : "l"(p + 1));
            asm volatile("ld.relaxed.gpu.global.b64 %0, [%1];" : "=l"(q2) : "l"(p + 2));
            asm volatile("ld.relaxed.gpu.global.b64 %0, [%1];" : "=l"(q3) : "l"(p + 3));
        } while ((unsigned)(q0 >> 32) != (unsigned)t ||
                 (unsigned)(q1 >> 32) != (unsigned)t ||
                 (unsigned)(q2 >> 32) != (unsigned)t ||
                 (unsigned)(q3 >> 32) != (unsigned)t);

        // 4. stage into SMEM
        float4 hv4;
        hv4.x = __uint_as_float((unsigned)q0);
        hv4.y = __uint_as_float((unsigned)q1);
        hv4.z = __uint_as_float((unsigned)q2);
        hv4.w = __uint_as_float((unsigned)q3);
        ((float4*)hs[cur])[tid] = hv4;
        __syncthreads();                     // bar B

        // 5. mat-vec: W_hh * h_t  +  W_ih * x_t  (all packed f32x2)
        unsigned long long a0 = 0ull, a1 = 0ull, a2 = 0ull, a3 = 0ull;
        const unsigned long long* h2p = (const unsigned long long*)hs[cur] + lane;
        #pragma unroll
        for (int k = 0; k < 16; k++) {
            unsigned long long hv = h2p[k * 32];
            FMA2(a0, wq[0][k], hv);
            FMA2(a1, wq[1][k], hv);
            FMA2(a2, wq[2][k], hv);
            FMA2(a3, wq[3][k], hv);
        }
        {
            unsigned long long xv = ((const unsigned long long*)xs[t % 3])[lane];
            FMA2(a0, wx[0], xv);
            FMA2(a1, wx[1], xv);
            FMA2(a2, wx[2], xv);
            FMA2(a3, wx[3], xv);
        }
        float s0, s1, s2, s3, xl, xh;
        upk2(a0, xl, xh); s0 = xl + xh;
        upk2(a1, xl, xh); s1 = xl + xh;
        upk2(a2, xl, xh); s2 = xl + xh;
        upk2(a3, xl, xh); s3 = xl + xh;

        #pragma unroll
        for (int off = 16; off > 0; off >>= 1) {
            s0 += __shfl_xor_sync(full, s0, off);
            s1 += __shfl_xor_sync(full, s1, off);
            s2 += __shfl_xor_sync(full, s2, off);
            s3 += __shfl_xor_sync(full, s3, off);
        }

        // 6. activations + publish (lane 0) — single atomic store = data+signal
        if (lane == 0) {
            const float i_ = sigf(s0 + bs0);
            const float f_ = sigf(s1 + bs1);
            const float g_ = tanhfast(s2 + bs2);
            const float o_ = sigf(s3 + bs3);
            c = fmaf(f_, c, i_ * g_);
            const float hnew = o_ * tanhfast(c);
            unsigned long long pub = pk_fu(hnew, (unsigned)(t + 1));
            asm volatile("st.relaxed.gpu.global.b64 [%0], %1;"
                         :: "l"(&g_hq[(t + 1) & 1][u]), "l"(pub));
        }

        // 7. trailing bar + single advisory counter bump
        __syncthreads();                     // bar C
        if (tid == 0)
            asm volatile("red.relaxed.gpu.global.add.u32 [%0], %1;"
                         :: "l"(&g_cnt), "r"(1u));
    }
}

// ---------------------------------------------------------------------------
// Kernel 2: out = h_S @ W_lin^T + b_lin   (O = 1)
// h_S lives in g_hq[S & 1] = g_hq[0] (tag field ignored)
// ---------------------------------------------------------------------------
__global__ void __launch_bounds__(1024) out_kernel(
    const float* __restrict__ Wlin,
    const float* __restrict__ blin,
    float* __restrict__ out)
{
    __shared__ float red[32];
    const int tid = threadIdx.x;
    float h = __uint_as_float((unsigned)(g_hq[0][tid] & 0xffffffffull));
    float v = h * Wlin[tid];
    #pragma unroll
    for (int off = 16; off > 0; off >>= 1)
        v += __shfl_xor_sync(0xffffffffu, v, off);
    if ((tid & 31) == 0) red[tid >> 5] = v;
    __syncthreads();
    if (tid < 32) {
        float xv = red[tid];
        #pragma unroll
        for (int off = 16; off > 0; off >>= 1)
            xv += __shfl_xor_sync(0xffffffffu, xv, off);
        if (tid == 0) out[0] = xv + blin[0];
    }
}

// ---------------------------------------------------------------------------
// kernel_launch (graph-capturable: plain launches only)
// Input order: input_seq, W_ih, W_hh, b_ih, b_hh, W_lin, b_lin (all fp32)
// ---------------------------------------------------------------------------
extern "C" void kernel_launch(void* const* d_in, const int* in_sizes, int n_in,
                              void* d_out, int out_size)
{
    const float* x    = (const float*)d_in[0];
    const float* Wih  = (const float*)d_in[1];
    const float* Whh  = (const float*)d_in[2];
    const float* bih  = (const float*)d_in[3];
    const float* bhh  = (const float*)d_in[4];
    const float* Wlin = (const float*)d_in[5];
    const float* blin = (const float*)d_in[6];
    float* out = (float*)d_out;

    reset_kernel<<<1, 1024>>>();
    rec_kernel<<<NCTA, 256>>>(x, Wih, Whh, bih, bhh);
    out_kernel<<<1, 1024>>>(Wlin, blin, out);
}

// round 17
// speedup vs baseline: 1.1167x; 1.1006x over previous
#include <cuda_runtime.h>
#include <cstdint>

// Problem sizes
#define S    4096
#define II   64
#define H    1024
#define NCTA 128
#define UPC  8        // hidden units per CTA (1 per warp, 8 warps)

// ---------------------------------------------------------------------------
// Device-global scratch (allocation-free rule: __device__ arrays only)
//
// CHAMPION R8 GLOBAL PROTOCOL — BYTE-IDENTICAL (9 variants all regressed):
//   g_hq: double-buffered tagged atoms {h:f32 | tag:u32}; h_t in slot t&1,
//         tag==t. st/ld.relaxed.gpu.b64 only (morally strong <=64b =>
//         single-copy atomic). Tags carry ALL correctness.
//   g_cnt: ADVISORY counter; exactly ONE polling lane per CTA (128 chip-
//         wide) + 128 relaxed REDs per step on ONE line.
// R17 delta vs R8: ONLY the activation computation is parallelized across
// lanes 0-3 (bit-identical math). Everything else untouched.
// ---------------------------------------------------------------------------
__device__ unsigned long long g_hq[2][H];
__device__ unsigned g_cnt;

// ---------------------------------------------------------------------------
// Helpers
// ---------------------------------------------------------------------------
__device__ __forceinline__ unsigned long long pk2(float x, float y) {
    unsigned long long r;
    asm("mov.b64 %0, {%1,%2};" : "=l"(r) : "f"(x), "f"(y));
    return r;
}
__device__ __forceinline__ void upk2(unsigned long long a, float& x, float& y) {
    asm("mov.b64 {%0,%1}, %2;" : "=f"(x), "=f"(y) : "l"(a));
}
__device__ __forceinline__ unsigned long long pk_fu(float x, unsigned t) {
    unsigned long long r;
    asm("mov.b64 %0, {%1,%2};" : "=l"(r) : "f"(x), "r"(t));
    return r;
}
#define FMA2(acc, a, b) \
    asm("fma.rn.f32x2 %0, %1, %2, %0;" : "+l"(acc) : "l"(a), "l"(b))

__device__ __forceinline__ float sigf(float x) {
    return 1.0f / (1.0f + __expf(-x));
}
__device__ __forceinline__ float tanhfast(float x) {
    float ax = fabsf(x);
    float e  = __expf(-2.0f * ax);          // in (0,1], overflow-free
    float t  = __fdividef(1.0f - e, 1.0f + e);
    return copysignf(t, x);
}

// ---------------------------------------------------------------------------
// Kernel 0: reset state between graph replays (determinism requirement)
// slot 0: tag 0 / h = 0  ->  step-0 poll passes immediately with h_0 = 0.
// ---------------------------------------------------------------------------
__global__ void reset_kernel() {
    int i = threadIdx.x;
    if (i < H) { g_hq[0][i] = 0ull; g_hq[1][i] = 0ull; }
    if (i == 0) g_cnt = 0u;
}

// ---------------------------------------------------------------------------
// Kernel 1: persistent fused LSTM recurrence (input GEMM folded in).
// 128 CTAs x 256 threads, 1 CTA/SM. Warp w of CTA b owns hidden unit
// u = b*8 + w (gate rows u, H+u, 2H+u, 3H+u). Lane l holds W_hh column
// pairs (2l+64k) k=0..15 (64 packed f32x2) + W_ih column pair 2l in regs.
//
// Per-step protocol (exactly the champion R8 rhythm, 3 bars):
//   1. prefetch x_{t+1} (tid<16, 256 B, triple-buffered SMEM)
//   2. GATE: tid 0 spins relaxed on advisory g_cnt until >= 128*t;
//      __syncthreads (bar A — parks warps, cheap wakeup)
//   3. SWEEP: 4 scalar ld.relaxed.b64 tagged atoms per thread; retry if a
//      tag is stale (rare post-gate) -> tag+data in one L2 round trip
//   4. stage h -> hs[t&1] (STS.128); __syncthreads (bar B)
//   5. matvec (LDS.64 + FMA2, W_hh + W_ih) -> butterfly shfl reduce
//   6. R17: lanes 0-3 compute the four gate activations CONCURRENTLY
//      (~40cy vs ~160cy serial); lane 0 gathers via 4 shfls, updates c,
//      publishes {h_new, t+1} via st.relaxed.gpu.b64 into slot (t+1)&1
//   7. __syncthreads (bar C); tid 0: red.relaxed.gpu.add(g_cnt, 1)
//
// Gate exactness: cnt >= 128t iff every CTA finished step t-1 (bar C
// orders each CTA's red after all 8 publishes). WAR on g_hq slots: a slot
// is rewritten only in step t+1, gated on cnt >= 128(t+1), which requires
// every reader's step-t red, ordered after that CTA's sweep reads of slot
// (t-1)&1 — the slot being clobbered; residual races caught by tag retry.
// Intra-CTA: 3 bars/step bound warp skew; hs double + xs triple buffers.
// ---------------------------------------------------------------------------
__global__ void __launch_bounds__(256, 1) rec_kernel(
    const float* __restrict__ x,
    const float* __restrict__ Wih,
    const float* __restrict__ Whh,
    const float* __restrict__ bih,
    const float* __restrict__ bhh)
{
    __shared__ __align__(16) float hs[2][H];     // staged h_t
    __shared__ __align__(16) float xs[3][II];    // staged x_t (triple buffer)

    const int tid  = threadIdx.x;
    const int lane = tid & 31;
    const int wrp  = tid >> 5;               // 0..7
    const int u    = blockIdx.x * UPC + wrp; // hidden unit 0..1023

    // ---- W_hh slice into registers (coalesced float2 loads) ----
    unsigned long long wq[4][16];
    #pragma unroll
    for (int g = 0; g < 4; g++) {
        const float2* base = (const float2*)(Whh + (size_t)(g * H + u) * H) + lane;
        #pragma unroll
        for (int k = 0; k < 16; k++) {
            float2 v = base[k * 32];
            wq[g][k] = pk2(v.x, v.y);
        }
    }
    // ---- W_ih slice (cols 2l, 2l+1 of rows u, H+u, 2H+u, 3H+u) ----
    unsigned long long wx[4];
    #pragma unroll
    for (int g = 0; g < 4; g++) {
        float2 v = ((const float2*)(Wih + (size_t)(g * H + u) * II))[lane];
        wx[g] = pk2(v.x, v.y);
    }
    // ---- biases (all lanes hold all four; lanes 0-3 use them) ----
    float bs0 = bih[u]         + bhh[u];
    float bs1 = bih[H + u]     + bhh[H + u];
    float bs2 = bih[2 * H + u] + bhh[2 * H + u];
    float bs3 = bih[3 * H + u] + bhh[3 * H + u];

    // ---- preload x_0 into xs[0] ----
    if (tid < 16) ((float4*)xs[0])[tid] = ((const float4*)x)[tid];
    __syncthreads();

    float c = 0.0f;                          // cell state (lane 0 only)
    const unsigned full = 0xffffffffu;

    const unsigned long long* mypoll = &g_hq[0][0] + 4 * tid;  // + slot*H per step

    #pragma unroll 1
    for (int t = 0; t < S; t++) {
        const int cur = t & 1;

        // 1. prefetch next step's input row (DRAM, hidden behind this step)
        if (t + 1 < S && tid < 16)
            ((float4*)xs[(t + 1) % 3])[tid] =
                __ldcg((const float4*)(x + (size_t)(t + 1) * II) + tid);

        // 2. GATE: single poller per CTA on the advisory counter (R8 exact)
        if (t > 0 && tid == 0) {
            const unsigned need = (unsigned)t * NCTA;
            unsigned v;
            do {
                asm volatile("ld.relaxed.gpu.global.u32 %0, [%1];"
                             : "=r"(v) : "l"(&g_cnt));
            } while (v < need);
        }
        __syncthreads();                     // bar A

        // 3. SWEEP: 4 tagged atoms per thread; retry only if a tag is stale
        const unsigned long long* p = mypoll + (size_t)cur * H;
        unsigned long long q0, q1, q2, q3;
        do {
            asm volatile("ld.relaxed.gpu.global.b64 %0, [%1];" : "=l"(q0) : "l"(p));
            asm volatile("ld.relaxed.gpu.global.b64 %0, [%1];" : "=l"(q1) : "l"(p + 1));
            asm volatile("ld.relaxed.gpu.global.b64 %0, [%1];" : "=l"(q2) : "l"(p + 2));
            asm volatile("ld.relaxed.gpu.global.b64 %0, [%1];" : "=l"(q3) : "l"(p + 3));
        } while ((unsigned)(q0 >> 32) != (unsigned)t ||
                 (unsigned)(q1 >> 32) != (unsigned)t ||
                 (unsigned)(q2 >> 32) != (unsigned)t ||
                 (unsigned)(q3 >> 32) != (unsigned)t);

        // 4. stage into SMEM
        float4 hv4;
        hv4.x = __uint_as_float((unsigned)q0);
        hv4.y = __uint_as_float((unsigned)q1);
        hv4.z = __uint_as_float((unsigned)q2);
        hv4.w = __uint_as_float((unsigned)q3);
        ((float4*)hs[cur])[tid] = hv4;
        __syncthreads();                     // bar B

        // 5. mat-vec: W_hh * h_t  +  W_ih * x_t  (all packed f32x2)
        unsigned long long a0 = 0ull, a1 = 0ull, a2 = 0ull, a3 = 0ull;
        const unsigned long long* h2p = (const unsigned long long*)hs[cur] + lane;
        #pragma unroll
        for (int k = 0; k < 16; k++) {
            unsigned long long hv = h2p[k * 32];
            FMA2(a0, wq[0][k], hv);
            FMA2(a1, wq[1][k], hv);
            FMA2(a2, wq[2][k], hv);
            FMA2(a3, wq[3][k], hv);
        }
        {
            unsigned long long xv = ((const unsigned long long*)xs[t % 3])[lane];
            FMA2(a0, wx[0], xv);
            FMA2(a1, wx[1], xv);
            FMA2(a2, wx[2], xv);
            FMA2(a3, wx[3], xv);
        }
        float s0, s1, s2, s3, xl, xh;
        upk2(a0, xl, xh); s0 = xl + xh;
        upk2(a1, xl, xh); s1 = xl + xh;
        upk2(a2, xl, xh); s2 = xl + xh;
        upk2(a3, xl, xh); s3 = xl + xh;

        #pragma unroll
        for (int off = 16; off > 0; off >>= 1) {
            s0 += __shfl_xor_sync(full, s0, off);
            s1 += __shfl_xor_sync(full, s1, off);
            s2 += __shfl_xor_sync(full, s2, off);
            s3 += __shfl_xor_sync(full, s3, off);
        }
        // post-butterfly: every lane holds the full s0..s3

        // 6. R17: parallel activations (lanes 0-3), gather, c-update, publish
        {
            const int r = lane & 3;
            float pre = (r == 0) ? s0 + bs0 :
                        (r == 1) ? s1 + bs1 :
                        (r == 2) ? s2 + bs2 : s3 + bs3;
            float act = (r == 2) ? tanhfast(pre) : sigf(pre);
            const float i_ = __shfl_sync(full, act, 0);
            const float f_ = __shfl_sync(full, act, 1);
            const float g_ = __shfl_sync(full, act, 2);
            const float o_ = __shfl_sync(full, act, 3);
            if (lane == 0) {
                c = fmaf(f_, c, i_ * g_);
                const float hnew = o_ * tanhfast(c);
                unsigned long long pub = pk_fu(hnew, (unsigned)(t + 1));
                asm volatile("st.relaxed.gpu.global.b64 [%0], %1;"
                             :: "l"(&g_hq[(t + 1) & 1][u]), "l"(pub));
            }
        }

        // 7. trailing bar + single advisory counter bump (R8 exact)
        __syncthreads();                     // bar C
        if (tid == 0)
            asm volatile("red.relaxed.gpu.global.add.u32 [%0], %1;"
                         :: "l"(&g_cnt), "r"(1u));
    }
}

// ---------------------------------------------------------------------------
// Kernel 2: out = h_S @ W_lin^T + b_lin   (O = 1)
// h_S lives in g_hq[S & 1] = g_hq[0] (tag field ignored)
// ---------------------------------------------------------------------------
__global__ void __launch_bounds__(1024) out_kernel(
    const float* __restrict__ Wlin,
    const float* __restrict__ blin,
    float* __restrict__ out)
{
    __shared__ float red[32];
    const int tid = threadIdx.x;
    float h = __uint_as_float((unsigned)(g_hq[0][tid] & 0xffffffffull));
    float v = h * Wlin[tid];
    #pragma unroll
    for (int off = 16; off > 0; off >>= 1)
        v += __shfl_xor_sync(0xffffffffu, v, off);
    if ((tid & 31) == 0) red[tid >> 5] = v;
    __syncthreads();
    if (tid < 32) {
        float xv = red[tid];
        #pragma unroll
        for (int off = 16; off > 0; off >>= 1)
            xv += __shfl_xor_sync(0xffffffffu, xv, off);
        if (tid == 0) out[0] = xv + blin[0];
    }
}

// ---------------------------------------------------------------------------
// kernel_launch (graph-capturable: plain launches only)
// Input order: input_seq, W_ih, W_hh, b_ih, b_hh, W_lin, b_lin (all fp32)
// ---------------------------------------------------------------------------
extern "C" void kernel_launch(void* const* d_in, const int* in_sizes, int n_in,
                              void* d_out, int out_size)
{
    const float* x    = (const float*)d_in[0];
    const float* Wih  = (const float*)d_in[1];
    const float* Whh  = (const float*)d_in[2];
    const float* bih  = (const float*)d_in[3];
    const float* bhh  = (const float*)d_in[4];
    const float* Wlin = (const float*)d_in[5];
    const float* blin = (const float*)d_in[6];
    float* out = (float*)d_out;

    reset_kernel<<<1, 1024>>>();
    rec_kernel<<<NCTA, 256>>>(x, Wih, Whh, bih, bhh);
    out_kernel<<<1, 1024>>>(Wlin, blin, out);
}